// round 9
// baseline (speedup 1.0000x reference)
#include <cuda_runtime.h>
#include <cstdint>
#include <cstddef>

#define EPSV  1e-6f
#define LNEPS 1e-5f

#define NB    4
#define LEN   16384
#define HN    8
#define DIM   16
#define ROWF  128          // HN*DIM floats per token row
#define ROW4  32           // float4 per token row
#define KVSZ  (HN*DIM*DIM) // 2048

#define CH1   64
#define R1    (LEN/CH1)    // 256 rows per p1 block
#define CH2   64
#define R2    (LEN/CH2)    // 256
#define CH3   64
#define R3    (LEN/CH3)    // 256 rows per p3 block
#define SUB   64
#define NSUB  (R3/SUB)     // 4
#define CH4   256          // p4 blocks per batch (64 tokens each)

// ---------------- scratch ----------------------------------------------------
__device__ float g_p1k[NB*CH1*ROWF];
__device__ float g_qsum [NB*ROWF];   // atomic accum (zeroed in p1)
__device__ float g_ksum [NB*ROWF];
__device__ float g_qnsum[NB*ROWF];   // atomic accum (zeroed in p1)
__device__ float g_knsum[NB*ROWF];   // atomic accum (zeroed in p1)
__device__ float g_kv[NB*KVSZ];      // atomic accum (zeroed in p1)
__device__ float g_se[NB*HN];        // atomic accum (zeroed in p1)

// ---------------- helpers -----------------------------------------------------
__device__ __forceinline__ float sigmoidf1(float x){
    float t;
    asm("tanh.approx.f32 %0, %1;" : "=f"(t) : "f"(0.5f*x));
    return fmaf(0.5f, t, 0.5f);
}
__device__ __forceinline__ float4 sigmoid4(float4 a){
    a.x = sigmoidf1(a.x); a.y = sigmoidf1(a.y);
    a.z = sigmoidf1(a.z); a.w = sigmoidf1(a.w);
    return a;
}
__device__ __forceinline__ void acc4(float4& x, float qd, float4 c){
    x.x = fmaf(qd, c.x, x.x); x.y = fmaf(qd, c.y, x.y);
    x.z = fmaf(qd, c.z, x.z); x.w = fmaf(qd, c.w, x.w);
}

// ---------------- pass 1: ksum partials (K only); zero accumulators ------------
__global__ void __launch_bounds__(256) p1_kernel(const float4* __restrict__ K4){
    int n = blockIdx.y, ch = blockIdx.x;
    int t = threadIdx.x;
    if (ch == 0){   // zero the atomic accumulators for this batch
        #pragma unroll
        for (int j = t; j < KVSZ; j += 256) g_kv[n*KVSZ + j] = 0.f;
        if (t < ROWF){
            g_qsum [n*ROWF + t] = 0.f;
            g_qnsum[n*ROWF + t] = 0.f;
            g_knsum[n*ROWF + t] = 0.f;
        }
        if (t < HN)  g_se[n*HN + t] = 0.f;
    }
    int c4 = t & 31, r0 = t >> 5;
    size_t base = ((size_t)n*LEN + (size_t)ch*R1)*ROW4 + c4;
    float4 ak = make_float4(0.f,0.f,0.f,0.f);
    #pragma unroll 4
    for (int ii = 0; ii < R1/8; ++ii){
        float4 k = sigmoid4(K4[base + (size_t)(r0 + ii*8)*ROW4]);
        ak.x += k.x; ak.y += k.y; ak.z += k.z; ak.w += k.w;
    }
    __shared__ float4 red[256];
    red[t] = ak;
    __syncthreads();
    if (t < 128){
        int cc = t >> 2, comp = t & 3;
        float s = 0.f;
        #pragma unroll
        for (int r = 0; r < 8; ++r) s += ((const float*)&red[r*32 + cc])[comp];
        g_p1k[(n*CH1 + ch)*ROWF + t] = s;
    }
}

// ---------------- pass 2: qsum + qnsum accumulate; finalize ksum ----------------
__global__ void __launch_bounds__(256) p2_kernel(const float4* __restrict__ Q4){
    __shared__ float sKs[ROWF];
    __shared__ float epsK[HN];
    __shared__ float4 red[256];
    int n = blockIdx.y, ch = blockIdx.x;
    int t = threadIdx.x;
    if (t < ROWF){
        float sk0 = 0.f, sk1 = 0.f;
        #pragma unroll
        for (int c = 0; c < CH1; c += 2){
            sk0 += g_p1k[(n*CH1+c  )*ROWF + t];
            sk1 += g_p1k[(n*CH1+c+1)*ROWF + t];
        }
        float sk = sk0 + sk1;
        sKs[t] = sk + EPSV;
        if (ch == 0) g_ksum[n*ROWF + t] = sk;
    }
    __syncthreads();
    if (t < HN){
        float a = 0.f;
        #pragma unroll
        for (int d = 0; d < DIM; ++d) a += sKs[t*DIM+d];
        epsK[t] = EPSV*a;
    }
    __syncthreads();
    int c4 = t & 31, r0 = t >> 5;
    int h = c4 >> 2;
    float4 ke = *(const float4*)&sKs[c4*4];
    float eK = epsK[h];
    size_t base = ((size_t)n*LEN + (size_t)ch*R2)*ROW4 + c4;
    float4 aq  = make_float4(0.f,0.f,0.f,0.f);   // sum q*nr
    float4 aqs = make_float4(0.f,0.f,0.f,0.f);   // sum q
    #pragma unroll 4
    for (int ii = 0; ii < R2/8; ++ii){
        float4 q = sigmoid4(Q4[base + (size_t)(r0 + ii*8)*ROW4]);
        float dq = q.x*ke.x + q.y*ke.y + q.z*ke.z + q.w*ke.w;
        dq += __shfl_xor_sync(0xffffffffu, dq, 1);
        dq += __shfl_xor_sync(0xffffffffu, dq, 2);
        float nr = __fdividef(1.f, dq + eK);
        aq.x = fmaf(q.x, nr, aq.x); aq.y = fmaf(q.y, nr, aq.y);
        aq.z = fmaf(q.z, nr, aq.z); aq.w = fmaf(q.w, nr, aq.w);
        aqs.x += q.x; aqs.y += q.y; aqs.z += q.z; aqs.w += q.w;
    }
    red[t] = aq;
    __syncthreads();
    if (t < 128){
        int cc = t >> 2, comp = t & 3;
        float s = 0.f;
        #pragma unroll
        for (int r = 0; r < 8; ++r) s += ((const float*)&red[r*32 + cc])[comp];
        atomicAdd(&g_qnsum[n*ROWF + t], s);
    }
    __syncthreads();
    red[t] = aqs;
    __syncthreads();
    if (t < 128){
        int cc = t >> 2, comp = t & 3;
        float s = 0.f;
        #pragma unroll
        for (int r = 0; r < 8; ++r) s += ((const float*)&red[r*32 + cc])[comp];
        atomicAdd(&g_qsum[n*ROWF + t], s);
    }
}

// ---------------- pass 3: kv, knsum, sumexp (atomic accumulate) -----------------
#define SM3_BYTES ((2*SUB*ROWF)*sizeof(float))

__global__ void __launch_bounds__(256) p3_kernel(const float4* __restrict__ K4,
                                                 const float4* __restrict__ V4){
    extern __shared__ float sm[];
    float* sk = sm;                    // SUB*ROWF   (holds w*k)
    float* sv = sm + SUB*ROWF;         // SUB*ROWF
    __shared__ float sQs[ROWF], qnE[ROWF];
    __shared__ float epsQ[HN], epsN[HN];
    int n = blockIdx.y, ch = blockIdx.x;
    int t = threadIdx.x;
    if (t < ROWF){
        sQs[t] = g_qsum [n*ROWF + t] + EPSV;
        qnE[t] = g_qnsum[n*ROWF + t] + EPSV;
    }
    __syncthreads();
    if (t < HN){
        float a = 0.f, b = 0.f;
        #pragma unroll
        for (int d = 0; d < DIM; ++d){ a += sQs[t*DIM+d]; b += qnE[t*DIM+d]; }
        epsQ[t] = EPSV*a; epsN[t] = EPSV*b;
    }
    __syncthreads();
    int c4 = t & 31, r0 = t >> 5;
    int h = c4 >> 2, q4i = c4 & 3;
    float4 qs4 = *(const float4*)&sQs[c4*4];
    float4 qn4 = *(const float4*)&qnE[c4*4];
    float eQ = epsQ[h], eN = epsN[h];
    int hh = t >> 5, idx = t & 31;
    int d = idx & 15, eh = idx >> 4;
    float a0=0.f,a1=0.f,a2=0.f,a3=0.f,a4=0.f,a5=0.f,a6=0.f,a7=0.f;
    float se = 0.f;
    float4 akn = make_float4(0.f,0.f,0.f,0.f);
    size_t base0 = ((size_t)n*LEN + (size_t)ch*R3)*ROW4 + c4;
    float4* sk4 = (float4*)sk;
    float4* sv4 = (float4*)sv;
    const float4* svr = (const float4*)sv;
    for (int sub = 0; sub < NSUB; ++sub){
        size_t base = base0 + (size_t)(sub*SUB)*ROW4;
        #pragma unroll
        for (int ii = 0; ii < SUB/8; ++ii){
            int i = r0 + ii*8;
            float4 k = sigmoid4(__ldcs(&K4[base + (size_t)i*ROW4]));  // K last use
            float4 v = V4[base + (size_t)i*ROW4];                     // keep V in L2
            sv4[i*ROW4 + c4] = v;
            float dk = k.x*qs4.x + k.y*qs4.y + k.z*qs4.z + k.w*qs4.w;
            float dn = k.x*qn4.x + k.y*qn4.y + k.z*qn4.z + k.w*qn4.w;
            dk += __shfl_xor_sync(0xffffffffu, dk, 1);
            dn += __shfl_xor_sync(0xffffffffu, dn, 1);
            dk += __shfl_xor_sync(0xffffffffu, dk, 2);
            dn += __shfl_xor_sync(0xffffffffu, dn, 2);
            float nc = __fdividef(1.f, dk + eQ);
            float w  = __expf(dn + eN);
            akn.x = fmaf(k.x, nc, akn.x); akn.y = fmaf(k.y, nc, akn.y);
            akn.z = fmaf(k.z, nc, akn.z); akn.w = fmaf(k.w, nc, akn.w);
            if (q4i == 0) se += w;
            k.x *= w; k.y *= w; k.z *= w; k.w *= w;   // premultiply
            sk4[i*ROW4 + c4] = k;
        }
        __syncthreads();
        #pragma unroll 4
        for (int s = 0; s < SUB; ++s){
            float wk = sk[s*ROWF + hh*DIM + d];
            float4 va = svr[s*ROW4 + hh*4 + eh*2];
            float4 vb = svr[s*ROW4 + hh*4 + eh*2 + 1];
            a0 = fmaf(wk, va.x, a0); a1 = fmaf(wk, va.y, a1);
            a2 = fmaf(wk, va.z, a2); a3 = fmaf(wk, va.w, a3);
            a4 = fmaf(wk, vb.x, a4); a5 = fmaf(wk, vb.y, a5);
            a6 = fmaf(wk, vb.z, a6); a7 = fmaf(wk, vb.w, a7);
        }
        __syncthreads();
    }
    // kv accumulate
    float* kvp = &g_kv[n*KVSZ + hh*(DIM*DIM) + d*DIM + eh*8];
    atomicAdd(kvp+0, a0); atomicAdd(kvp+1, a1);
    atomicAdd(kvp+2, a2); atomicAdd(kvp+3, a3);
    atomicAdd(kvp+4, a4); atomicAdd(kvp+5, a5);
    atomicAdd(kvp+6, a6); atomicAdd(kvp+7, a7);
    // sumexp block-reduce (sv region as scratch)
    sv[t] = (q4i == 0) ? se : 0.f;
    // knsum block reduce (sk region as scratch)
    float4* red4 = (float4*)sk;
    red4[t] = akn;
    __syncthreads();
    if (t < HN){
        float s = 0.f;
        #pragma unroll
        for (int r = 0; r < 8; ++r) s += sv[r*32 + t*4];
        atomicAdd(&g_se[n*HN + t], s);
    }
    if (t < 128){
        int cc = t >> 2, comp = t & 3;
        float s = 0.f;
        #pragma unroll
        for (int r = 0; r < 8; ++r) s += ((const float*)&red4[r*32 + cc])[comp];
        atomicAdd(&g_knsum[n*ROWF + t], s);
    }
}

// ---------------- pass 4: 2-token ILP, q+v prefetch, shuffle-rotate matvec ------
__global__ void __launch_bounds__(256, 2) p4_kernel(const float4* __restrict__ Q4,
                                                    const float4* __restrict__ V4,
                                                    const float*  __restrict__ gma,
                                                    const float*  __restrict__ bta,
                                                    float4* __restrict__ O4){
    __shared__ float kvs[KVSZ];   // 8 KB
    __shared__ float sKs[ROWF], sKn[ROWF];
    __shared__ float epsK[HN], epsN[HN], sScale[HN];
    __shared__ float sg[DIM], sb[DIM];
    int n = blockIdx.y, ch = blockIdx.x;
    int t = threadIdx.x;
    #pragma unroll
    for (int i = t; i < KVSZ; i += 256) kvs[i] = g_kv[n*KVSZ + i];
    if (t < ROWF){
        sKs[t] = g_ksum [n*ROWF + t] + EPSV;
        sKn[t] = g_knsum[n*ROWF + t] + EPSV;
    }
    if (t < DIM){ sg[t] = gma[t]; sb[t] = bta[t]; }
    if (t < HN) sScale[t] = (float)LEN / g_se[n*HN + t];  // softmax*S scale
    __syncthreads();
    if (t < HN){
        float a = 0.f, bb = 0.f;
        #pragma unroll
        for (int d = 0; d < DIM; ++d){ a += sKs[t*DIM+d]; bb += sKn[t*DIM+d]; }
        epsK[t] = EPSV*a; epsN[t] = EPSV*bb;
    }
    __syncthreads();
    int warp = t >> 5, lane = t & 31;
    int h = lane >> 2, c = lane & 3;
    float4 kvr[16];   // [round r][j] = kv[d=(c^r)*4+j][e-chunk c]
    #pragma unroll
    for (int r = 0; r < 4; ++r){
        int ds = (c ^ r) * 4;
        #pragma unroll
        for (int j = 0; j < 4; ++j)
            kvr[r*4+j] = *(const float4*)&kvs[h*256 + (ds+j)*DIM + c*4];
    }
    float4 Ksl = *(const float4*)&sKs[h*DIM + c*4];
    float4 Knl = *(const float4*)&sKn[h*DIM + c*4];
    float eK = epsK[h], eN = epsN[h], scl = sScale[h];
    size_t base = ((size_t)n*LEN + (size_t)ch*64 + (size_t)warp*8)*ROW4 + lane;
    const float4* Qp = Q4 + base;
    const float4* Vp = V4 + base;
    float4*       Op = O4 + base;
    float4 qc0 = __ldcs(&Qp[0]);
    float4 qc1 = __ldcs(&Qp[ROW4]);
    float4 vc0 = __ldcs(&Vp[0]);
    float4 vc1 = __ldcs(&Vp[ROW4]);
    #pragma unroll
    for (int it = 0; it < 4; ++it){
        float4 nq0, nq1, nv0, nv1;
        if (it < 3){
            nq0 = __ldcs(&Qp[(it*2+2)*ROW4]);
            nq1 = __ldcs(&Qp[(it*2+3)*ROW4]);
            nv0 = __ldcs(&Vp[(it*2+2)*ROW4]);
            nv1 = __ldcs(&Vp[(it*2+3)*ROW4]);
        }
        float4 q0 = sigmoid4(qc0);
        float4 q1 = sigmoid4(qc1);
        float pr0 = q0.x*Ksl.x + q0.y*Ksl.y + q0.z*Ksl.z + q0.w*Ksl.w;
        float pn0 = q0.x*Knl.x + q0.y*Knl.y + q0.z*Knl.z + q0.w*Knl.w;
        float pr1 = q1.x*Ksl.x + q1.y*Ksl.y + q1.z*Ksl.z + q1.w*Ksl.w;
        float pn1 = q1.x*Knl.x + q1.y*Knl.y + q1.z*Knl.z + q1.w*Knl.w;
        pr0 += __shfl_xor_sync(0xffffffffu, pr0, 1);
        pn0 += __shfl_xor_sync(0xffffffffu, pn0, 1);
        pr1 += __shfl_xor_sync(0xffffffffu, pr1, 1);
        pn1 += __shfl_xor_sync(0xffffffffu, pn1, 1);
        pr0 += __shfl_xor_sync(0xffffffffu, pr0, 2);
        pn0 += __shfl_xor_sync(0xffffffffu, pn0, 2);
        pr1 += __shfl_xor_sync(0xffffffffu, pr1, 2);
        pn1 += __shfl_xor_sync(0xffffffffu, pn1, 2);
        float sc0 = __fdividef(scl, pr0 + eK) * sigmoidf1(pn0 + eN);
        float sc1 = __fdividef(scl, pr1 + eK) * sigmoidf1(pn1 + eN);
        float4 x0 = make_float4(0.f,0.f,0.f,0.f);
        float4 x1 = make_float4(0.f,0.f,0.f,0.f);
        acc4(x0, q0.x, kvr[0]); acc4(x1, q1.x, kvr[0]);
        acc4(x0, q0.y, kvr[1]); acc4(x1, q1.y, kvr[1]);
        acc4(x0, q0.z, kvr[2]); acc4(x1, q1.z, kvr[2]);
        acc4(x0, q0.w, kvr[3]); acc4(x1, q1.w, kvr[3]);
        #pragma unroll
        for (int r = 1; r < 4; ++r){
            float4 qs0, qs1;
            qs0.x = __shfl_xor_sync(0xffffffffu, q0.x, r);
            qs1.x = __shfl_xor_sync(0xffffffffu, q1.x, r);
            qs0.y = __shfl_xor_sync(0xffffffffu, q0.y, r);
            qs1.y = __shfl_xor_sync(0xffffffffu, q1.y, r);
            qs0.z = __shfl_xor_sync(0xffffffffu, q0.z, r);
            qs1.z = __shfl_xor_sync(0xffffffffu, q1.z, r);
            qs0.w = __shfl_xor_sync(0xffffffffu, q0.w, r);
            qs1.w = __shfl_xor_sync(0xffffffffu, q1.w, r);
            acc4(x0, qs0.x, kvr[r*4+0]); acc4(x1, qs1.x, kvr[r*4+0]);
            acc4(x0, qs0.y, kvr[r*4+1]); acc4(x1, qs1.y, kvr[r*4+1]);
            acc4(x0, qs0.z, kvr[r*4+2]); acc4(x1, qs1.z, kvr[r*4+2]);
            acc4(x0, qs0.w, kvr[r*4+3]); acc4(x1, qs1.w, kvr[r*4+3]);
        }
        x0.x = fmaf(x0.x, sc0, vc0.x); x0.y = fmaf(x0.y, sc0, vc0.y);
        x0.z = fmaf(x0.z, sc0, vc0.z); x0.w = fmaf(x0.w, sc0, vc0.w);
        x1.x = fmaf(x1.x, sc1, vc1.x); x1.y = fmaf(x1.y, sc1, vc1.y);
        x1.z = fmaf(x1.z, sc1, vc1.z); x1.w = fmaf(x1.w, sc1, vc1.w);
        float m0 = (x0.x + x0.y) + (x0.z + x0.w);
        float m1 = (x1.x + x1.y) + (x1.z + x1.w);
        m0 += __shfl_xor_sync(0xffffffffu, m0, 1);
        m1 += __shfl_xor_sync(0xffffffffu, m1, 1);
        m0 += __shfl_xor_sync(0xffffffffu, m0, 2);
        m1 += __shfl_xor_sync(0xffffffffu, m1, 2);
        m0 *= 0.0625f; m1 *= 0.0625f;
        x0.x -= m0; x0.y -= m0; x0.z -= m0; x0.w -= m0;
        x1.x -= m1; x1.y -= m1; x1.z -= m1; x1.w -= m1;
        float va0 = x0.x*x0.x, va1 = x1.x*x1.x;
        va0 = fmaf(x0.y, x0.y, va0); va1 = fmaf(x1.y, x1.y, va1);
        va0 = fmaf(x0.z, x0.z, va0); va1 = fmaf(x1.z, x1.z, va1);
        va0 = fmaf(x0.w, x0.w, va0); va1 = fmaf(x1.w, x1.w, va1);
        va0 += __shfl_xor_sync(0xffffffffu, va0, 1);
        va1 += __shfl_xor_sync(0xffffffffu, va1, 1);
        va0 += __shfl_xor_sync(0xffffffffu, va0, 2);
        va1 += __shfl_xor_sync(0xffffffffu, va1, 2);
        float rs0 = rsqrtf(fmaf(va0, 0.0625f, LNEPS));
        float rs1 = rsqrtf(fmaf(va1, 0.0625f, LNEPS));
        // gamma/beta from smem (off critical path; saves 8 registers)
        float4 gl = *(const float4*)&sg[c*4];
        float4 bl = *(const float4*)&sb[c*4];
        float4 o0, o1;
        o0.x = fmaf(x0.x*rs0, gl.x, bl.x); o0.y = fmaf(x0.y*rs0, gl.y, bl.y);
        o0.z = fmaf(x0.z*rs0, gl.z, bl.z); o0.w = fmaf(x0.w*rs0, gl.w, bl.w);
        o1.x = fmaf(x1.x*rs1, gl.x, bl.x); o1.y = fmaf(x1.y*rs1, gl.y, bl.y);
        o1.z = fmaf(x1.z*rs1, gl.z, bl.z); o1.w = fmaf(x1.w*rs1, gl.w, bl.w);
        __stcs(&Op[(it*2  )*ROW4], o0);
        __stcs(&Op[(it*2+1)*ROW4], o1);
        qc0 = nq0; qc1 = nq1;
        vc0 = nv0; vc1 = nv1;
    }
}

// ---------------- launcher ------------------------------------------------------
extern "C" void kernel_launch(void* const* d_in, const int* in_sizes, int n_in,
                              void* d_out, int out_size){
    (void)in_sizes; (void)n_in; (void)out_size;
    const float4* Q = (const float4*)d_in[0];
    const float4* K = (const float4*)d_in[1];
    const float4* V = (const float4*)d_in[2];
    const float*  G = (const float*) d_in[3];
    const float*  B = (const float*) d_in[4];
    float4* O = (float4*)d_out;

    static bool attr_done = false;
    if (!attr_done){
        cudaFuncSetAttribute(p3_kernel, cudaFuncAttributeMaxDynamicSharedMemorySize,
                             (int)SM3_BYTES);
        attr_done = true;
    }

    dim3 g1(CH1, NB), g2(CH2, NB), g3(CH3, NB), g4(CH4, NB);
    p1_kernel<<<g1, 256>>>(K);
    p2_kernel<<<g2, 256>>>(Q);
    p3_kernel<<<g3, 256, SM3_BYTES>>>(K, V);
    p4_kernel<<<g4, 256>>>(Q, V, G, B, O);
}

// round 10
// speedup vs baseline: 1.0180x; 1.0180x over previous
#include <cuda_runtime.h>
#include <cstdint>
#include <cstddef>

#define EPSV  1e-6f
#define LNEPS 1e-5f

#define NB    4
#define LEN   16384
#define HN    8
#define DIM   16
#define ROWF  128          // HN*DIM floats per token row
#define ROW4  32           // float4 per token row
#define KVSZ  (HN*DIM*DIM) // 2048

#define CH1   64
#define R1    (LEN/CH1)    // 256 rows per p1 block
#define CH2   64
#define R2    (LEN/CH2)    // 256
#define CH3   64
#define R3    (LEN/CH3)    // 256 rows per p3 block
#define SUB   64
#define NSUB  (R3/SUB)     // 4
#define CH4   256          // p4 blocks per batch (64 tokens each)

// ---------------- scratch ----------------------------------------------------
__device__ float g_p1k[NB*CH1*ROWF];
__device__ float g_qsum [NB*ROWF];   // atomic accum (zeroed in p1)
__device__ float g_ksum [NB*ROWF];
__device__ float g_qnsum[NB*ROWF];   // atomic accum (zeroed in p1)
__device__ float g_knsum[NB*ROWF];   // atomic accum (zeroed in p1)
__device__ float g_kv[NB*KVSZ];      // atomic accum (zeroed in p1)
__device__ float g_se[NB*HN];        // atomic accum (zeroed in p1)

// ---------------- helpers -----------------------------------------------------
__device__ __forceinline__ float sigmoidf1(float x){
    float t;
    asm("tanh.approx.f32 %0, %1;" : "=f"(t) : "f"(0.5f*x));
    return fmaf(0.5f, t, 0.5f);
}
__device__ __forceinline__ float4 sigmoid4(float4 a){
    a.x = sigmoidf1(a.x); a.y = sigmoidf1(a.y);
    a.z = sigmoidf1(a.z); a.w = sigmoidf1(a.w);
    return a;
}
__device__ __forceinline__ void acc4(float4& x, float qd, float4 c){
    x.x = fmaf(qd, c.x, x.x); x.y = fmaf(qd, c.y, x.y);
    x.z = fmaf(qd, c.z, x.z); x.w = fmaf(qd, c.w, x.w);
}

// ---------------- pass 1: ksum partials (K only); zero accumulators ------------
__global__ void __launch_bounds__(256) p1_kernel(const float4* __restrict__ K4){
    int n = blockIdx.y, ch = blockIdx.x;
    int t = threadIdx.x;
    if (ch == 0){   // zero the atomic accumulators for this batch
        #pragma unroll
        for (int j = t; j < KVSZ; j += 256) g_kv[n*KVSZ + j] = 0.f;
        if (t < ROWF){
            g_qsum [n*ROWF + t] = 0.f;
            g_qnsum[n*ROWF + t] = 0.f;
            g_knsum[n*ROWF + t] = 0.f;
        }
        if (t < HN)  g_se[n*HN + t] = 0.f;
    }
    int c4 = t & 31, r0 = t >> 5;
    size_t base = ((size_t)n*LEN + (size_t)ch*R1)*ROW4 + c4;
    float4 ak = make_float4(0.f,0.f,0.f,0.f);
    #pragma unroll 4
    for (int ii = 0; ii < R1/8; ++ii){
        float4 k = sigmoid4(K4[base + (size_t)(r0 + ii*8)*ROW4]);
        ak.x += k.x; ak.y += k.y; ak.z += k.z; ak.w += k.w;
    }
    __shared__ float4 red[256];
    red[t] = ak;
    __syncthreads();
    if (t < 128){
        int cc = t >> 2, comp = t & 3;
        float s = 0.f;
        #pragma unroll
        for (int r = 0; r < 8; ++r) s += ((const float*)&red[r*32 + cc])[comp];
        g_p1k[(n*CH1 + ch)*ROWF + t] = s;
    }
}

// ---------------- pass 2: qsum + qnsum accumulate; finalize ksum ----------------
__global__ void __launch_bounds__(256) p2_kernel(const float4* __restrict__ Q4){
    __shared__ float sKs[ROWF];
    __shared__ float epsK[HN];
    __shared__ float4 red[256];
    int n = blockIdx.y, ch = blockIdx.x;
    int t = threadIdx.x;
    if (t < ROWF){
        float sk0 = 0.f, sk1 = 0.f;
        #pragma unroll
        for (int c = 0; c < CH1; c += 2){
            sk0 += g_p1k[(n*CH1+c  )*ROWF + t];
            sk1 += g_p1k[(n*CH1+c+1)*ROWF + t];
        }
        float sk = sk0 + sk1;
        sKs[t] = sk + EPSV;
        if (ch == 0) g_ksum[n*ROWF + t] = sk;
    }
    __syncthreads();
    if (t < HN){
        float a = 0.f;
        #pragma unroll
        for (int d = 0; d < DIM; ++d) a += sKs[t*DIM+d];
        epsK[t] = EPSV*a;
    }
    __syncthreads();
    int c4 = t & 31, r0 = t >> 5;
    int h = c4 >> 2;
    float4 ke = *(const float4*)&sKs[c4*4];
    float eK = epsK[h];
    size_t base = ((size_t)n*LEN + (size_t)ch*R2)*ROW4 + c4;
    float4 aq  = make_float4(0.f,0.f,0.f,0.f);   // sum q*nr
    float4 aqs = make_float4(0.f,0.f,0.f,0.f);   // sum q
    #pragma unroll 4
    for (int ii = 0; ii < R2/8; ++ii){
        float4 q = sigmoid4(Q4[base + (size_t)(r0 + ii*8)*ROW4]);
        float dq = q.x*ke.x + q.y*ke.y + q.z*ke.z + q.w*ke.w;
        dq += __shfl_xor_sync(0xffffffffu, dq, 1);
        dq += __shfl_xor_sync(0xffffffffu, dq, 2);
        float nr = __fdividef(1.f, dq + eK);
        aq.x = fmaf(q.x, nr, aq.x); aq.y = fmaf(q.y, nr, aq.y);
        aq.z = fmaf(q.z, nr, aq.z); aq.w = fmaf(q.w, nr, aq.w);
        aqs.x += q.x; aqs.y += q.y; aqs.z += q.z; aqs.w += q.w;
    }
    red[t] = aq;
    __syncthreads();
    if (t < 128){
        int cc = t >> 2, comp = t & 3;
        float s = 0.f;
        #pragma unroll
        for (int r = 0; r < 8; ++r) s += ((const float*)&red[r*32 + cc])[comp];
        atomicAdd(&g_qnsum[n*ROWF + t], s);
    }
    __syncthreads();
    red[t] = aqs;
    __syncthreads();
    if (t < 128){
        int cc = t >> 2, comp = t & 3;
        float s = 0.f;
        #pragma unroll
        for (int r = 0; r < 8; ++r) s += ((const float*)&red[r*32 + cc])[comp];
        atomicAdd(&g_qsum[n*ROWF + t], s);
    }
}

// ---------------- pass 3: kv, knsum, sumexp (atomic accumulate) -----------------
#define SM3_BYTES ((2*SUB*ROWF)*sizeof(float))

__global__ void __launch_bounds__(256) p3_kernel(const float4* __restrict__ K4,
                                                 const float4* __restrict__ V4){
    extern __shared__ float sm[];
    float* sk = sm;                    // SUB*ROWF   (holds w*k)
    float* sv = sm + SUB*ROWF;         // SUB*ROWF
    __shared__ float sQs[ROWF], qnE[ROWF];
    __shared__ float epsQ[HN], epsN[HN];
    int n = blockIdx.y, ch = blockIdx.x;
    int t = threadIdx.x;
    if (t < ROWF){
        sQs[t] = g_qsum [n*ROWF + t] + EPSV;
        qnE[t] = g_qnsum[n*ROWF + t] + EPSV;
    }
    __syncthreads();
    if (t < HN){
        float a = 0.f, b = 0.f;
        #pragma unroll
        for (int d = 0; d < DIM; ++d){ a += sQs[t*DIM+d]; b += qnE[t*DIM+d]; }
        epsQ[t] = EPSV*a; epsN[t] = EPSV*b;
    }
    __syncthreads();
    int c4 = t & 31, r0 = t >> 5;
    int h = c4 >> 2, q4i = c4 & 3;
    float4 qs4 = *(const float4*)&sQs[c4*4];
    float4 qn4 = *(const float4*)&qnE[c4*4];
    float eQ = epsQ[h], eN = epsN[h];
    int hh = t >> 5, idx = t & 31;
    int d = idx & 15, eh = idx >> 4;
    float a0=0.f,a1=0.f,a2=0.f,a3=0.f,a4=0.f,a5=0.f,a6=0.f,a7=0.f;
    float se = 0.f;
    float4 akn = make_float4(0.f,0.f,0.f,0.f);
    size_t base0 = ((size_t)n*LEN + (size_t)ch*R3)*ROW4 + c4;
    float4* sk4 = (float4*)sk;
    float4* sv4 = (float4*)sv;
    const float4* svr = (const float4*)sv;
    for (int sub = 0; sub < NSUB; ++sub){
        size_t base = base0 + (size_t)(sub*SUB)*ROW4;
        #pragma unroll
        for (int ii = 0; ii < SUB/8; ++ii){
            int i = r0 + ii*8;
            float4 k = sigmoid4(__ldcs(&K4[base + (size_t)i*ROW4]));  // K last use
            float4 v = V4[base + (size_t)i*ROW4];                     // keep V in L2
            sv4[i*ROW4 + c4] = v;
            float dk = k.x*qs4.x + k.y*qs4.y + k.z*qs4.z + k.w*qs4.w;
            float dn = k.x*qn4.x + k.y*qn4.y + k.z*qn4.z + k.w*qn4.w;
            dk += __shfl_xor_sync(0xffffffffu, dk, 1);
            dn += __shfl_xor_sync(0xffffffffu, dn, 1);
            dk += __shfl_xor_sync(0xffffffffu, dk, 2);
            dn += __shfl_xor_sync(0xffffffffu, dn, 2);
            float nc = __fdividef(1.f, dk + eQ);
            float w  = __expf(dn + eN);
            akn.x = fmaf(k.x, nc, akn.x); akn.y = fmaf(k.y, nc, akn.y);
            akn.z = fmaf(k.z, nc, akn.z); akn.w = fmaf(k.w, nc, akn.w);
            if (q4i == 0) se += w;
            k.x *= w; k.y *= w; k.z *= w; k.w *= w;   // premultiply
            sk4[i*ROW4 + c4] = k;
        }
        __syncthreads();
        #pragma unroll 4
        for (int s = 0; s < SUB; ++s){
            float wk = sk[s*ROWF + hh*DIM + d];
            float4 va = svr[s*ROW4 + hh*4 + eh*2];
            float4 vb = svr[s*ROW4 + hh*4 + eh*2 + 1];
            a0 = fmaf(wk, va.x, a0); a1 = fmaf(wk, va.y, a1);
            a2 = fmaf(wk, va.z, a2); a3 = fmaf(wk, va.w, a3);
            a4 = fmaf(wk, vb.x, a4); a5 = fmaf(wk, vb.y, a5);
            a6 = fmaf(wk, vb.z, a6); a7 = fmaf(wk, vb.w, a7);
        }
        __syncthreads();
    }
    // kv accumulate
    float* kvp = &g_kv[n*KVSZ + hh*(DIM*DIM) + d*DIM + eh*8];
    atomicAdd(kvp+0, a0); atomicAdd(kvp+1, a1);
    atomicAdd(kvp+2, a2); atomicAdd(kvp+3, a3);
    atomicAdd(kvp+4, a4); atomicAdd(kvp+5, a5);
    atomicAdd(kvp+6, a6); atomicAdd(kvp+7, a7);
    // sumexp block-reduce (sv region as scratch)
    sv[t] = (q4i == 0) ? se : 0.f;
    // knsum block reduce (sk region as scratch)
    float4* red4 = (float4*)sk;
    red4[t] = akn;
    __syncthreads();
    if (t < HN){
        float s = 0.f;
        #pragma unroll
        for (int r = 0; r < 8; ++r) s += sv[r*32 + t*4];
        atomicAdd(&g_se[n*HN + t], s);
    }
    if (t < 128){
        int cc = t >> 2, comp = t & 3;
        float s = 0.f;
        #pragma unroll
        for (int r = 0; r < 8; ++r) s += ((const float*)&red4[r*32 + cc])[comp];
        atomicAdd(&g_knsum[n*ROWF + t], s);
    }
}

// ---------------- pass 4: 2-token ILP, q+v prefetch, shuffle-rotate matvec ------
__global__ void __launch_bounds__(256, 2) p4_kernel(const float4* __restrict__ Q4,
                                                    const float4* __restrict__ V4,
                                                    const float*  __restrict__ gma,
                                                    const float*  __restrict__ bta,
                                                    float4* __restrict__ O4){
    __shared__ float kvs[KVSZ];   // 8 KB
    __shared__ float sKs[ROWF], sKn[ROWF];
    __shared__ float epsK[HN], epsN[HN], sScale[HN];
    __shared__ float sg[DIM], sb[DIM];
    int n = blockIdx.y, ch = blockIdx.x;
    int t = threadIdx.x;
    #pragma unroll
    for (int i = t; i < KVSZ; i += 256) kvs[i] = g_kv[n*KVSZ + i];
    if (t < ROWF){
        sKs[t] = g_ksum [n*ROWF + t] + EPSV;
        sKn[t] = g_knsum[n*ROWF + t] + EPSV;
    }
    if (t < DIM){ sg[t] = gma[t]; sb[t] = bta[t]; }
    if (t < HN) sScale[t] = (float)LEN / g_se[n*HN + t];  // softmax*S scale
    __syncthreads();
    if (t < HN){
        float a = 0.f, bb = 0.f;
        #pragma unroll
        for (int d = 0; d < DIM; ++d){ a += sKs[t*DIM+d]; bb += sKn[t*DIM+d]; }
        epsK[t] = EPSV*a; epsN[t] = EPSV*bb;
    }
    __syncthreads();
    int warp = t >> 5, lane = t & 31;
    int h = lane >> 2, c = lane & 3;
    float4 kvr[16];   // [round r][j] = kv[d=(c^r)*4+j][e-chunk c]
    #pragma unroll
    for (int r = 0; r < 4; ++r){
        int ds = (c ^ r) * 4;
        #pragma unroll
        for (int j = 0; j < 4; ++j)
            kvr[r*4+j] = *(const float4*)&kvs[h*256 + (ds+j)*DIM + c*4];
    }
    float4 Ksl = *(const float4*)&sKs[h*DIM + c*4];
    float4 Knl = *(const float4*)&sKn[h*DIM + c*4];
    float eK = epsK[h], eN = epsN[h], scl = sScale[h];
    size_t base = ((size_t)n*LEN + (size_t)ch*64 + (size_t)warp*8)*ROW4 + lane;
    const float4* Qp = Q4 + base;
    const float4* Vp = V4 + base;
    float4*       Op = O4 + base;
    float4 qc0 = __ldcs(&Qp[0]);
    float4 qc1 = __ldcs(&Qp[ROW4]);
    float4 vc0 = __ldcs(&Vp[0]);
    float4 vc1 = __ldcs(&Vp[ROW4]);
    #pragma unroll
    for (int it = 0; it < 4; ++it){
        float4 nq0, nq1, nv0, nv1;
        if (it < 3){
            nq0 = __ldcs(&Qp[(it*2+2)*ROW4]);
            nq1 = __ldcs(&Qp[(it*2+3)*ROW4]);
            nv0 = __ldcs(&Vp[(it*2+2)*ROW4]);
            nv1 = __ldcs(&Vp[(it*2+3)*ROW4]);
        }
        float4 q0 = sigmoid4(qc0);
        float4 q1 = sigmoid4(qc1);
        float pr0 = q0.x*Ksl.x + q0.y*Ksl.y + q0.z*Ksl.z + q0.w*Ksl.w;
        float pn0 = q0.x*Knl.x + q0.y*Knl.y + q0.z*Knl.z + q0.w*Knl.w;
        float pr1 = q1.x*Ksl.x + q1.y*Ksl.y + q1.z*Ksl.z + q1.w*Ksl.w;
        float pn1 = q1.x*Knl.x + q1.y*Knl.y + q1.z*Knl.z + q1.w*Knl.w;
        pr0 += __shfl_xor_sync(0xffffffffu, pr0, 1);
        pn0 += __shfl_xor_sync(0xffffffffu, pn0, 1);
        pr1 += __shfl_xor_sync(0xffffffffu, pr1, 1);
        pn1 += __shfl_xor_sync(0xffffffffu, pn1, 1);
        pr0 += __shfl_xor_sync(0xffffffffu, pr0, 2);
        pn0 += __shfl_xor_sync(0xffffffffu, pn0, 2);
        pr1 += __shfl_xor_sync(0xffffffffu, pr1, 2);
        pn1 += __shfl_xor_sync(0xffffffffu, pn1, 2);
        float sc0 = __fdividef(scl, pr0 + eK) * sigmoidf1(pn0 + eN);
        float sc1 = __fdividef(scl, pr1 + eK) * sigmoidf1(pn1 + eN);
        float4 x0 = make_float4(0.f,0.f,0.f,0.f);
        float4 x1 = make_float4(0.f,0.f,0.f,0.f);
        acc4(x0, q0.x, kvr[0]); acc4(x1, q1.x, kvr[0]);
        acc4(x0, q0.y, kvr[1]); acc4(x1, q1.y, kvr[1]);
        acc4(x0, q0.z, kvr[2]); acc4(x1, q1.z, kvr[2]);
        acc4(x0, q0.w, kvr[3]); acc4(x1, q1.w, kvr[3]);
        #pragma unroll
        for (int r = 1; r < 4; ++r){
            float4 qs0, qs1;
            qs0.x = __shfl_xor_sync(0xffffffffu, q0.x, r);
            qs1.x = __shfl_xor_sync(0xffffffffu, q1.x, r);
            qs0.y = __shfl_xor_sync(0xffffffffu, q0.y, r);
            qs1.y = __shfl_xor_sync(0xffffffffu, q1.y, r);
            qs0.z = __shfl_xor_sync(0xffffffffu, q0.z, r);
            qs1.z = __shfl_xor_sync(0xffffffffu, q1.z, r);
            qs0.w = __shfl_xor_sync(0xffffffffu, q0.w, r);
            qs1.w = __shfl_xor_sync(0xffffffffu, q1.w, r);
            acc4(x0, qs0.x, kvr[r*4+0]); acc4(x1, qs1.x, kvr[r*4+0]);
            acc4(x0, qs0.y, kvr[r*4+1]); acc4(x1, qs1.y, kvr[r*4+1]);
            acc4(x0, qs0.z, kvr[r*4+2]); acc4(x1, qs1.z, kvr[r*4+2]);
            acc4(x0, qs0.w, kvr[r*4+3]); acc4(x1, qs1.w, kvr[r*4+3]);
        }
        x0.x = fmaf(x0.x, sc0, vc0.x); x0.y = fmaf(x0.y, sc0, vc0.y);
        x0.z = fmaf(x0.z, sc0, vc0.z); x0.w = fmaf(x0.w, sc0, vc0.w);
        x1.x = fmaf(x1.x, sc1, vc1.x); x1.y = fmaf(x1.y, sc1, vc1.y);
        x1.z = fmaf(x1.z, sc1, vc1.z); x1.w = fmaf(x1.w, sc1, vc1.w);
        float m0 = (x0.x + x0.y) + (x0.z + x0.w);
        float m1 = (x1.x + x1.y) + (x1.z + x1.w);
        m0 += __shfl_xor_sync(0xffffffffu, m0, 1);
        m1 += __shfl_xor_sync(0xffffffffu, m1, 1);
        m0 += __shfl_xor_sync(0xffffffffu, m0, 2);
        m1 += __shfl_xor_sync(0xffffffffu, m1, 2);
        m0 *= 0.0625f; m1 *= 0.0625f;
        x0.x -= m0; x0.y -= m0; x0.z -= m0; x0.w -= m0;
        x1.x -= m1; x1.y -= m1; x1.z -= m1; x1.w -= m1;
        float va0 = x0.x*x0.x, va1 = x1.x*x1.x;
        va0 = fmaf(x0.y, x0.y, va0); va1 = fmaf(x1.y, x1.y, va1);
        va0 = fmaf(x0.z, x0.z, va0); va1 = fmaf(x1.z, x1.z, va1);
        va0 = fmaf(x0.w, x0.w, va0); va1 = fmaf(x1.w, x1.w, va1);
        va0 += __shfl_xor_sync(0xffffffffu, va0, 1);
        va1 += __shfl_xor_sync(0xffffffffu, va1, 1);
        va0 += __shfl_xor_sync(0xffffffffu, va0, 2);
        va1 += __shfl_xor_sync(0xffffffffu, va1, 2);
        float rs0 = rsqrtf(fmaf(va0, 0.0625f, LNEPS));
        float rs1 = rsqrtf(fmaf(va1, 0.0625f, LNEPS));
        // gamma/beta from smem (off critical path; saves 8 registers)
        float4 gl = *(const float4*)&sg[c*4];
        float4 bl = *(const float4*)&sb[c*4];
        float4 o0, o1;
        o0.x = fmaf(x0.x*rs0, gl.x, bl.x); o0.y = fmaf(x0.y*rs0, gl.y, bl.y);
        o0.z = fmaf(x0.z*rs0, gl.z, bl.z); o0.w = fmaf(x0.w*rs0, gl.w, bl.w);
        o1.x = fmaf(x1.x*rs1, gl.x, bl.x); o1.y = fmaf(x1.y*rs1, gl.y, bl.y);
        o1.z = fmaf(x1.z*rs1, gl.z, bl.z); o1.w = fmaf(x1.w*rs1, gl.w, bl.w);
        __stcs(&Op[(it*2  )*ROW4], o0);
        __stcs(&Op[(it*2+1)*ROW4], o1);
        qc0 = nq0; qc1 = nq1;
        vc0 = nv0; vc1 = nv1;
    }
}

// ---------------- launcher ------------------------------------------------------
extern "C" void kernel_launch(void* const* d_in, const int* in_sizes, int n_in,
                              void* d_out, int out_size){
    (void)in_sizes; (void)n_in; (void)out_size;
    const float4* Q = (const float4*)d_in[0];
    const float4* K = (const float4*)d_in[1];
    const float4* V = (const float4*)d_in[2];
    const float*  G = (const float*) d_in[3];
    const float*  B = (const float*) d_in[4];
    float4* O = (float4*)d_out;

    static bool attr_done = false;
    if (!attr_done){
        cudaFuncSetAttribute(p3_kernel, cudaFuncAttributeMaxDynamicSharedMemorySize,
                             (int)SM3_BYTES);
        attr_done = true;
    }

    dim3 g1(CH1, NB), g2(CH2, NB), g3(CH3, NB), g4(CH4, NB);
    p1_kernel<<<g1, 256>>>(K);
    p2_kernel<<<g2, 256>>>(Q);
    p3_kernel<<<g3, 256, SM3_BYTES>>>(K, V);
    p4_kernel<<<g4, 256>>>(Q, V, G, B, O);
}

// round 11
// speedup vs baseline: 1.0248x; 1.0067x over previous
#include <cuda_runtime.h>
#include <cstdint>
#include <cstddef>

#define EPSV  1e-6f
#define LNEPS 1e-5f

#define NB    4
#define LEN   16384
#define HN    8
#define DIM   16
#define ROWF  128          // HN*DIM floats per token row
#define ROW4  32           // float4 per token row
#define KVSZ  (HN*DIM*DIM) // 2048

#define CH1   64
#define R1    (LEN/CH1)    // 256 rows per p1 block
#define CH2   64
#define R2    (LEN/CH2)    // 256
#define CH3   64
#define R3    (LEN/CH3)    // 256 rows per p3 block
#define SUB   64
#define NSUB  (R3/SUB)     // 4
#define CH4   256          // p4 blocks per batch (64 tokens each)

typedef unsigned long long u64;

// ---------------- scratch ----------------------------------------------------
__device__ float g_p1k[NB*CH1*ROWF];
__device__ float g_qsum [NB*ROWF];   // atomic accum (zeroed in p1)
__device__ float g_ksum [NB*ROWF];
__device__ float g_qnsum[NB*ROWF];   // atomic accum (zeroed in p1)
__device__ float g_knsum[NB*ROWF];   // atomic accum (zeroed in p1)
__device__ float g_kv[NB*KVSZ];      // atomic accum (zeroed in p1)
__device__ float g_se[NB*HN];        // atomic accum (zeroed in p1)

// ---------------- helpers -----------------------------------------------------
__device__ __forceinline__ float sigmoidf1(float x){
    float t;
    asm("tanh.approx.f32 %0, %1;" : "=f"(t) : "f"(0.5f*x));
    return fmaf(0.5f, t, 0.5f);
}
__device__ __forceinline__ float4 sigmoid4(float4 a){
    a.x = sigmoidf1(a.x); a.y = sigmoidf1(a.y);
    a.z = sigmoidf1(a.z); a.w = sigmoidf1(a.w);
    return a;
}
// ---- packed f32x2 (Blackwell FFMA2; exact fp32, 2 lanes per issue slot) ----
__device__ __forceinline__ u64 pack2(float x){
    u64 r; asm("mov.b64 %0, {%1, %1};" : "=l"(r) : "f"(x)); return r;
}
__device__ __forceinline__ void fma2(u64& d, u64 a, u64 b){
    asm("fma.rn.f32x2 %0, %1, %2, %0;" : "+l"(d) : "l"(a), "l"(b));
}
__device__ __forceinline__ u64 fma2g(u64 a, u64 b, u64 c){
    u64 d; asm("fma.rn.f32x2 %0, %1, %2, %3;" : "=l"(d) : "l"(a), "l"(b), "l"(c));
    return d;
}
__device__ __forceinline__ float2 unpack2(u64 v){
    float2 f; asm("mov.b64 {%0, %1}, %2;" : "=f"(f.x), "=f"(f.y) : "l"(v)); return f;
}

// ---------------- pass 1: ksum partials (K only); zero accumulators ------------
__global__ void __launch_bounds__(256) p1_kernel(const float4* __restrict__ K4){
    int n = blockIdx.y, ch = blockIdx.x;
    int t = threadIdx.x;
    if (ch == 0){   // zero the atomic accumulators for this batch
        #pragma unroll
        for (int j = t; j < KVSZ; j += 256) g_kv[n*KVSZ + j] = 0.f;
        if (t < ROWF){
            g_qsum [n*ROWF + t] = 0.f;
            g_qnsum[n*ROWF + t] = 0.f;
            g_knsum[n*ROWF + t] = 0.f;
        }
        if (t < HN)  g_se[n*HN + t] = 0.f;
    }
    int c4 = t & 31, r0 = t >> 5;
    size_t base = ((size_t)n*LEN + (size_t)ch*R1)*ROW4 + c4;
    float4 ak = make_float4(0.f,0.f,0.f,0.f);
    #pragma unroll 4
    for (int ii = 0; ii < R1/8; ++ii){
        float4 k = sigmoid4(K4[base + (size_t)(r0 + ii*8)*ROW4]);
        ak.x += k.x; ak.y += k.y; ak.z += k.z; ak.w += k.w;
    }
    __shared__ float4 red[256];
    red[t] = ak;
    __syncthreads();
    if (t < 128){
        int cc = t >> 2, comp = t & 3;
        float s = 0.f;
        #pragma unroll
        for (int r = 0; r < 8; ++r) s += ((const float*)&red[r*32 + cc])[comp];
        g_p1k[(n*CH1 + ch)*ROWF + t] = s;
    }
}

// ---------------- pass 2: qsum + qnsum accumulate; finalize ksum ----------------
__global__ void __launch_bounds__(256) p2_kernel(const float4* __restrict__ Q4){
    __shared__ float sKs[ROWF];
    __shared__ float epsK[HN];
    __shared__ float4 red[256];
    int n = blockIdx.y, ch = blockIdx.x;
    int t = threadIdx.x;
    if (t < ROWF){
        float sk0 = 0.f, sk1 = 0.f;
        #pragma unroll
        for (int c = 0; c < CH1; c += 2){
            sk0 += g_p1k[(n*CH1+c  )*ROWF + t];
            sk1 += g_p1k[(n*CH1+c+1)*ROWF + t];
        }
        float sk = sk0 + sk1;
        sKs[t] = sk + EPSV;
        if (ch == 0) g_ksum[n*ROWF + t] = sk;
    }
    __syncthreads();
    if (t < HN){
        float a = 0.f;
        #pragma unroll
        for (int d = 0; d < DIM; ++d) a += sKs[t*DIM+d];
        epsK[t] = EPSV*a;
    }
    __syncthreads();
    int c4 = t & 31, r0 = t >> 5;
    int h = c4 >> 2;
    float4 ke = *(const float4*)&sKs[c4*4];
    float eK = epsK[h];
    size_t base = ((size_t)n*LEN + (size_t)ch*R2)*ROW4 + c4;
    float4 aq  = make_float4(0.f,0.f,0.f,0.f);   // sum q*nr
    float4 aqs = make_float4(0.f,0.f,0.f,0.f);   // sum q
    #pragma unroll 4
    for (int ii = 0; ii < R2/8; ++ii){
        float4 q = sigmoid4(Q4[base + (size_t)(r0 + ii*8)*ROW4]);
        float dq = q.x*ke.x + q.y*ke.y + q.z*ke.z + q.w*ke.w;
        dq += __shfl_xor_sync(0xffffffffu, dq, 1);
        dq += __shfl_xor_sync(0xffffffffu, dq, 2);
        float nr = __fdividef(1.f, dq + eK);
        aq.x = fmaf(q.x, nr, aq.x); aq.y = fmaf(q.y, nr, aq.y);
        aq.z = fmaf(q.z, nr, aq.z); aq.w = fmaf(q.w, nr, aq.w);
        aqs.x += q.x; aqs.y += q.y; aqs.z += q.z; aqs.w += q.w;
    }
    red[t] = aq;
    __syncthreads();
    if (t < 128){
        int cc = t >> 2, comp = t & 3;
        float s = 0.f;
        #pragma unroll
        for (int r = 0; r < 8; ++r) s += ((const float*)&red[r*32 + cc])[comp];
        atomicAdd(&g_qnsum[n*ROWF + t], s);
    }
    __syncthreads();
    red[t] = aqs;
    __syncthreads();
    if (t < 128){
        int cc = t >> 2, comp = t & 3;
        float s = 0.f;
        #pragma unroll
        for (int r = 0; r < 8; ++r) s += ((const float*)&red[r*32 + cc])[comp];
        atomicAdd(&g_qsum[n*ROWF + t], s);
    }
}

// ---------------- pass 3: kv, knsum, sumexp (atomic accumulate) -----------------
#define SM3_BYTES ((2*SUB*ROWF)*sizeof(float))

__global__ void __launch_bounds__(256) p3_kernel(const float4* __restrict__ K4,
                                                 const float4* __restrict__ V4){
    extern __shared__ float sm[];
    float* sk = sm;                    // SUB*ROWF   (holds w*k)
    float* sv = sm + SUB*ROWF;         // SUB*ROWF
    __shared__ float sQs[ROWF], qnE[ROWF];
    __shared__ float epsQ[HN], epsN[HN];
    int n = blockIdx.y, ch = blockIdx.x;
    int t = threadIdx.x;
    if (t < ROWF){
        sQs[t] = g_qsum [n*ROWF + t] + EPSV;
        qnE[t] = g_qnsum[n*ROWF + t] + EPSV;
    }
    __syncthreads();
    if (t < HN){
        float a = 0.f, b = 0.f;
        #pragma unroll
        for (int d = 0; d < DIM; ++d){ a += sQs[t*DIM+d]; b += qnE[t*DIM+d]; }
        epsQ[t] = EPSV*a; epsN[t] = EPSV*b;
    }
    __syncthreads();
    int c4 = t & 31, r0 = t >> 5;
    int h = c4 >> 2, q4i = c4 & 3;
    float4 qs4 = *(const float4*)&sQs[c4*4];
    float4 qn4 = *(const float4*)&qnE[c4*4];
    float eQ = epsQ[h], eN = epsN[h];
    int hh = t >> 5, idx = t & 31;
    int d = idx & 15, eh = idx >> 4;
    u64 aA = 0ull, aB = 0ull, aC = 0ull, aD = 0ull;   // packed f32x2 accumulators
    float se = 0.f;
    float4 akn = make_float4(0.f,0.f,0.f,0.f);
    size_t base0 = ((size_t)n*LEN + (size_t)ch*R3)*ROW4 + c4;
    float4* sk4 = (float4*)sk;
    float4* sv4 = (float4*)sv;
    const double2* svd = (const double2*)sv;
    for (int sub = 0; sub < NSUB; ++sub){
        size_t base = base0 + (size_t)(sub*SUB)*ROW4;
        #pragma unroll
        for (int ii = 0; ii < SUB/8; ++ii){
            int i = r0 + ii*8;
            float4 k = sigmoid4(__ldcs(&K4[base + (size_t)i*ROW4]));  // K last use
            float4 v = V4[base + (size_t)i*ROW4];                     // keep V in L2
            sv4[i*ROW4 + c4] = v;
            float dk = k.x*qs4.x + k.y*qs4.y + k.z*qs4.z + k.w*qs4.w;
            float dn = k.x*qn4.x + k.y*qn4.y + k.z*qn4.z + k.w*qn4.w;
            dk += __shfl_xor_sync(0xffffffffu, dk, 1);
            dn += __shfl_xor_sync(0xffffffffu, dn, 1);
            dk += __shfl_xor_sync(0xffffffffu, dk, 2);
            dn += __shfl_xor_sync(0xffffffffu, dn, 2);
            float nc = __fdividef(1.f, dk + eQ);
            float w  = __expf(dn + eN);
            akn.x = fmaf(k.x, nc, akn.x); akn.y = fmaf(k.y, nc, akn.y);
            akn.z = fmaf(k.z, nc, akn.z); akn.w = fmaf(k.w, nc, akn.w);
            if (q4i == 0) se += w;
            k.x *= w; k.y *= w; k.z *= w; k.w *= w;   // premultiply
            sk4[i*ROW4 + c4] = k;
        }
        __syncthreads();
        #pragma unroll 4
        for (int s = 0; s < SUB; ++s){
            float wk = sk[s*ROWF + hh*DIM + d];
            u64 w2 = pack2(wk);
            double2 va = svd[s*ROW4 + hh*4 + eh*2];
            double2 vb = svd[s*ROW4 + hh*4 + eh*2 + 1];
            fma2(aA, w2, __double_as_longlong(va.x));
            fma2(aB, w2, __double_as_longlong(va.y));
            fma2(aC, w2, __double_as_longlong(vb.x));
            fma2(aD, w2, __double_as_longlong(vb.y));
        }
        __syncthreads();
    }
    // unpack packed accumulators
    float2 f;
    float a0,a1,a2,a3,a4,a5,a6,a7;
    f = unpack2(aA); a0 = f.x; a1 = f.y;
    f = unpack2(aB); a2 = f.x; a3 = f.y;
    f = unpack2(aC); a4 = f.x; a5 = f.y;
    f = unpack2(aD); a6 = f.x; a7 = f.y;
    // kv accumulate
    float* kvp = &g_kv[n*KVSZ + hh*(DIM*DIM) + d*DIM + eh*8];
    atomicAdd(kvp+0, a0); atomicAdd(kvp+1, a1);
    atomicAdd(kvp+2, a2); atomicAdd(kvp+3, a3);
    atomicAdd(kvp+4, a4); atomicAdd(kvp+5, a5);
    atomicAdd(kvp+6, a6); atomicAdd(kvp+7, a7);
    // sumexp block-reduce (sv region as scratch)
    sv[t] = (q4i == 0) ? se : 0.f;
    // knsum block reduce (sk region as scratch)
    float4* red4 = (float4*)sk;
    red4[t] = akn;
    __syncthreads();
    if (t < HN){
        float s = 0.f;
        #pragma unroll
        for (int r = 0; r < 8; ++r) s += sv[r*32 + t*4];
        atomicAdd(&g_se[n*HN + t], s);
    }
    if (t < 128){
        int cc = t >> 2, comp = t & 3;
        float s = 0.f;
        #pragma unroll
        for (int r = 0; r < 8; ++r) s += ((const float*)&red4[r*32 + cc])[comp];
        atomicAdd(&g_knsum[n*ROWF + t], s);
    }
}

// ---------------- pass 4: 2-token ILP, f32x2 matvec, shuffle-rotate -------------
__global__ void __launch_bounds__(256, 2) p4_kernel(const float4* __restrict__ Q4,
                                                    const float4* __restrict__ V4,
                                                    const float*  __restrict__ gma,
                                                    const float*  __restrict__ bta,
                                                    float4* __restrict__ O4){
    __shared__ float kvs[KVSZ];   // 8 KB
    __shared__ float sKs[ROWF], sKn[ROWF];
    __shared__ float epsK[HN], epsN[HN], sScale[HN];
    __shared__ float sg[DIM], sb[DIM];
    int n = blockIdx.y, ch = blockIdx.x;
    int t = threadIdx.x;
    #pragma unroll
    for (int i = t; i < KVSZ; i += 256) kvs[i] = g_kv[n*KVSZ + i];
    if (t < ROWF){
        sKs[t] = g_ksum [n*ROWF + t] + EPSV;
        sKn[t] = g_knsum[n*ROWF + t] + EPSV;
    }
    if (t < DIM){ sg[t] = gma[t]; sb[t] = bta[t]; }
    if (t < HN) sScale[t] = (float)LEN / g_se[n*HN + t];  // softmax*S scale
    __syncthreads();
    if (t < HN){
        float a = 0.f, bb = 0.f;
        #pragma unroll
        for (int d = 0; d < DIM; ++d){ a += sKs[t*DIM+d]; bb += sKn[t*DIM+d]; }
        epsK[t] = EPSV*a; epsN[t] = EPSV*bb;
    }
    __syncthreads();
    int warp = t >> 5, lane = t & 31;
    int h = lane >> 2, c = lane & 3;
    // kv tile in registers as f32x2 pairs: kvr[i*2], kvr[i*2+1] for i = r*4+j
    u64 kvr[32];
    #pragma unroll
    for (int r = 0; r < 4; ++r){
        int ds = (c ^ r) * 4;
        #pragma unroll
        for (int j = 0; j < 4; ++j){
            double2 kd = *(const double2*)&kvs[h*256 + (ds+j)*DIM + c*4];
            kvr[(r*4+j)*2  ] = __double_as_longlong(kd.x);
            kvr[(r*4+j)*2+1] = __double_as_longlong(kd.y);
        }
    }
    float4 Ksl = *(const float4*)&sKs[h*DIM + c*4];
    float4 Knl = *(const float4*)&sKn[h*DIM + c*4];
    float eK = epsK[h], eN = epsN[h], scl = sScale[h];
    size_t base = ((size_t)n*LEN + (size_t)ch*64 + (size_t)warp*8)*ROW4 + lane;
    const float4*  Qp = Q4 + base;
    const double2* Vp = (const double2*)(V4 + base);
    float4*        Op = O4 + base;
    float4 qc0 = __ldcs(&Qp[0]);
    float4 qc1 = __ldcs(&Qp[ROW4]);
    #pragma unroll
    for (int it = 0; it < 4; ++it){
        float4 nq0, nq1;
        if (it < 3){
            nq0 = __ldcs(&Qp[(it*2+2)*ROW4]);
            nq1 = __ldcs(&Qp[(it*2+3)*ROW4]);
        }
        double2 vv0 = __ldcs(&Vp[(it*2  )*ROW4]);
        double2 vv1 = __ldcs(&Vp[(it*2+1)*ROW4]);
        float4 q0 = sigmoid4(qc0);
        float4 q1 = sigmoid4(qc1);
        float pr0 = q0.x*Ksl.x + q0.y*Ksl.y + q0.z*Ksl.z + q0.w*Ksl.w;
        float pn0 = q0.x*Knl.x + q0.y*Knl.y + q0.z*Knl.z + q0.w*Knl.w;
        float pr1 = q1.x*Ksl.x + q1.y*Ksl.y + q1.z*Ksl.z + q1.w*Ksl.w;
        float pn1 = q1.x*Knl.x + q1.y*Knl.y + q1.z*Knl.z + q1.w*Knl.w;
        pr0 += __shfl_xor_sync(0xffffffffu, pr0, 1);
        pn0 += __shfl_xor_sync(0xffffffffu, pn0, 1);
        pr1 += __shfl_xor_sync(0xffffffffu, pr1, 1);
        pn1 += __shfl_xor_sync(0xffffffffu, pn1, 1);
        pr0 += __shfl_xor_sync(0xffffffffu, pr0, 2);
        pn0 += __shfl_xor_sync(0xffffffffu, pn0, 2);
        pr1 += __shfl_xor_sync(0xffffffffu, pr1, 2);
        pn1 += __shfl_xor_sync(0xffffffffu, pn1, 2);
        float sc0 = __fdividef(scl, pr0 + eK) * sigmoidf1(pn0 + eN);
        float sc1 = __fdividef(scl, pr1 + eK) * sigmoidf1(pn1 + eN);
        u64 x0a = 0ull, x0b = 0ull, x1a = 0ull, x1b = 0ull;
        u64 p;
        // round 0: own q
        p = pack2(q0.x); fma2(x0a, p, kvr[0]); fma2(x0b, p, kvr[1]);
        p = pack2(q1.x); fma2(x1a, p, kvr[0]); fma2(x1b, p, kvr[1]);
        p = pack2(q0.y); fma2(x0a, p, kvr[2]); fma2(x0b, p, kvr[3]);
        p = pack2(q1.y); fma2(x1a, p, kvr[2]); fma2(x1b, p, kvr[3]);
        p = pack2(q0.z); fma2(x0a, p, kvr[4]); fma2(x0b, p, kvr[5]);
        p = pack2(q1.z); fma2(x1a, p, kvr[4]); fma2(x1b, p, kvr[5]);
        p = pack2(q0.w); fma2(x0a, p, kvr[6]); fma2(x0b, p, kvr[7]);
        p = pack2(q1.w); fma2(x1a, p, kvr[6]); fma2(x1b, p, kvr[7]);
        #pragma unroll
        for (int r = 1; r < 4; ++r){
            float4 qs0, qs1;
            qs0.x = __shfl_xor_sync(0xffffffffu, q0.x, r);
            qs1.x = __shfl_xor_sync(0xffffffffu, q1.x, r);
            qs0.y = __shfl_xor_sync(0xffffffffu, q0.y, r);
            qs1.y = __shfl_xor_sync(0xffffffffu, q1.y, r);
            qs0.z = __shfl_xor_sync(0xffffffffu, q0.z, r);
            qs1.z = __shfl_xor_sync(0xffffffffu, q1.z, r);
            qs0.w = __shfl_xor_sync(0xffffffffu, q0.w, r);
            qs1.w = __shfl_xor_sync(0xffffffffu, q1.w, r);
            p = pack2(qs0.x); fma2(x0a, p, kvr[r*8+0]); fma2(x0b, p, kvr[r*8+1]);
            p = pack2(qs1.x); fma2(x1a, p, kvr[r*8+0]); fma2(x1b, p, kvr[r*8+1]);
            p = pack2(qs0.y); fma2(x0a, p, kvr[r*8+2]); fma2(x0b, p, kvr[r*8+3]);
            p = pack2(qs1.y); fma2(x1a, p, kvr[r*8+2]); fma2(x1b, p, kvr[r*8+3]);
            p = pack2(qs0.z); fma2(x0a, p, kvr[r*8+4]); fma2(x0b, p, kvr[r*8+5]);
            p = pack2(qs1.z); fma2(x1a, p, kvr[r*8+4]); fma2(x1b, p, kvr[r*8+5]);
            p = pack2(qs0.w); fma2(x0a, p, kvr[r*8+6]); fma2(x0b, p, kvr[r*8+7]);
            p = pack2(qs1.w); fma2(x1a, p, kvr[r*8+6]); fma2(x1b, p, kvr[r*8+7]);
        }
        // residual (packed): x = x*sc + v
        u64 s0 = pack2(sc0), s1 = pack2(sc1);
        x0a = fma2g(x0a, s0, __double_as_longlong(vv0.x));
        x0b = fma2g(x0b, s0, __double_as_longlong(vv0.y));
        x1a = fma2g(x1a, s1, __double_as_longlong(vv1.x));
        x1b = fma2g(x1b, s1, __double_as_longlong(vv1.y));
        float4 x0, x1;
        float2 f;
        f = unpack2(x0a); x0.x = f.x; x0.y = f.y;
        f = unpack2(x0b); x0.z = f.x; x0.w = f.y;
        f = unpack2(x1a); x1.x = f.x; x1.y = f.y;
        f = unpack2(x1b); x1.z = f.x; x1.w = f.y;
        float m0 = (x0.x + x0.y) + (x0.z + x0.w);
        float m1 = (x1.x + x1.y) + (x1.z + x1.w);
        m0 += __shfl_xor_sync(0xffffffffu, m0, 1);
        m1 += __shfl_xor_sync(0xffffffffu, m1, 1);
        m0 += __shfl_xor_sync(0xffffffffu, m0, 2);
        m1 += __shfl_xor_sync(0xffffffffu, m1, 2);
        m0 *= 0.0625f; m1 *= 0.0625f;
        x0.x -= m0; x0.y -= m0; x0.z -= m0; x0.w -= m0;
        x1.x -= m1; x1.y -= m1; x1.z -= m1; x1.w -= m1;
        float va0 = x0.x*x0.x, va1 = x1.x*x1.x;
        va0 = fmaf(x0.y, x0.y, va0); va1 = fmaf(x1.y, x1.y, va1);
        va0 = fmaf(x0.z, x0.z, va0); va1 = fmaf(x1.z, x1.z, va1);
        va0 = fmaf(x0.w, x0.w, va0); va1 = fmaf(x1.w, x1.w, va1);
        va0 += __shfl_xor_sync(0xffffffffu, va0, 1);
        va1 += __shfl_xor_sync(0xffffffffu, va1, 1);
        va0 += __shfl_xor_sync(0xffffffffu, va0, 2);
        va1 += __shfl_xor_sync(0xffffffffu, va1, 2);
        float rs0 = rsqrtf(fmaf(va0, 0.0625f, LNEPS));
        float rs1 = rsqrtf(fmaf(va1, 0.0625f, LNEPS));
        // gamma/beta from smem (off critical path)
        float4 gl = *(const float4*)&sg[c*4];
        float4 bl = *(const float4*)&sb[c*4];
        float4 o0, o1;
        o0.x = fmaf(x0.x*rs0, gl.x, bl.x); o0.y = fmaf(x0.y*rs0, gl.y, bl.y);
        o0.z = fmaf(x0.z*rs0, gl.z, bl.z); o0.w = fmaf(x0.w*rs0, gl.w, bl.w);
        o1.x = fmaf(x1.x*rs1, gl.x, bl.x); o1.y = fmaf(x1.y*rs1, gl.y, bl.y);
        o1.z = fmaf(x1.z*rs1, gl.z, bl.z); o1.w = fmaf(x1.w*rs1, gl.w, bl.w);
        __stcs(&Op[(it*2  )*ROW4], o0);
        __stcs(&Op[(it*2+1)*ROW4], o1);
        qc0 = nq0; qc1 = nq1;
    }
}

// ---------------- launcher ------------------------------------------------------
extern "C" void kernel_launch(void* const* d_in, const int* in_sizes, int n_in,
                              void* d_out, int out_size){
    (void)in_sizes; (void)n_in; (void)out_size;
    const float4* Q = (const float4*)d_in[0];
    const float4* K = (const float4*)d_in[1];
    const float4* V = (const float4*)d_in[2];
    const float*  G = (const float*) d_in[3];
    const float*  B = (const float*) d_in[4];
    float4* O = (float4*)d_out;

    static bool attr_done = false;
    if (!attr_done){
        cudaFuncSetAttribute(p3_kernel, cudaFuncAttributeMaxDynamicSharedMemorySize,
                             (int)SM3_BYTES);
        attr_done = true;
    }

    dim3 g1(CH1, NB), g2(CH2, NB), g3(CH3, NB), g4(CH4, NB);
    p1_kernel<<<g1, 256>>>(K);
    p2_kernel<<<g2, 256>>>(Q);
    p3_kernel<<<g3, 256, SM3_BYTES>>>(K, V);
    p4_kernel<<<g4, 256>>>(Q, V, G, B, O);
}